// round 2
// baseline (speedup 1.0000x reference)
#include <cuda_runtime.h>
#include <cuda_bf16.h>
#include <cstdint>
#include <cstddef>

// ---------------- problem constants ----------------
#define INDIM  1024
#define OUTDIM 2048
#define BATCH  8192

#define BM 128
#define BN 128
#define BK 64                    // bf16 elems per stage = 128 B row (swizzle atom)
#define NSTAGE_K (INDIM / BK)    // 16
#define STAGES 4
#define GEMM_THREADS 256

// SMEM: [0,512) p_sq tile, [1024,...) STAGES x (A BM*128B | B BN*128B)
#define SMEM_PSQ_OFF   0u
#define SMEM_TILES_OFF 1024u
#define STAGE_BYTES    ((BM + BN) * 128u)                    // 32768
#define SMEM_TOTAL     (SMEM_TILES_OFF + STAGES * STAGE_BYTES)  // 132096

// ---------------- device scratch (alloc-free) ----------------
__device__ __align__(128) __nv_bfloat16 g_x_bf16[(size_t)BATCH * INDIM];   // 16 MB
__device__ __align__(128) __nv_bfloat16 g_pt_bf16[(size_t)OUTDIM * INDIM]; // 4 MB, [n][k]
__device__ float g_x_sq[BATCH];
__device__ float g_p_sq[OUTDIM];

// ---------------- helpers ----------------
__device__ __forceinline__ uint32_t smem_to_u32(const void* p) {
    uint32_t a;
    asm("{ .reg .u64 t; cvta.to.shared.u64 t, %1; cvt.u32.u64 %0, t; }" : "=r"(a) : "l"(p));
    return a;
}
__device__ __forceinline__ uint32_t sw128(uint32_t off) {
    return off ^ ((off >> 3) & 0x70);
}
__device__ __forceinline__ void cp_async16(uint32_t dst, const void* src) {
    asm volatile("cp.async.cg.shared.global [%0], [%1], 16;" :: "r"(dst), "l"(src) : "memory");
}
#define CP_COMMIT() asm volatile("cp.async.commit_group;" ::: "memory")
#define CP_WAIT(n)  asm volatile("cp.async.wait_group %0;" :: "n"(n) : "memory")

__device__ __forceinline__ void ldmatrix_x4(uint32_t* r, uint32_t addr) {
    asm volatile("ldmatrix.sync.aligned.m8n8.x4.shared.b16 {%0,%1,%2,%3}, [%4];"
                 : "=r"(r[0]), "=r"(r[1]), "=r"(r[2]), "=r"(r[3]) : "r"(addr));
}
__device__ __forceinline__ void mma_bf16(float* c, const uint32_t* a, const uint32_t* b) {
    asm volatile(
        "mma.sync.aligned.m16n8k16.row.col.f32.bf16.bf16.f32 "
        "{%0,%1,%2,%3}, {%4,%5,%6,%7}, {%8,%9}, {%0,%1,%2,%3};"
        : "+f"(c[0]), "+f"(c[1]), "+f"(c[2]), "+f"(c[3])
        : "r"(a[0]), "r"(a[1]), "r"(a[2]), "r"(a[3]), "r"(b[0]), "r"(b[1]));
}

// ---------------- prep kernels ----------------
__global__ void convert_x_kernel(const float* __restrict__ x) {
    int row = blockIdx.x;
    int tid = threadIdx.x;
    const float* xr = x + (size_t)row * INDIM;
    __nv_bfloat16* dst = g_x_bf16 + (size_t)row * INDIM;
    float acc = 0.f;
#pragma unroll
    for (int i = 0; i < INDIM / 256; i++) {
        float v = xr[tid + i * 256];
        acc += v * v;
        dst[tid + i * 256] = __float2bfloat16(v);
    }
#pragma unroll
    for (int o = 16; o > 0; o >>= 1) acc += __shfl_xor_sync(0xFFFFFFFFu, acc, o);
    __shared__ float red[8];
    if ((tid & 31) == 0) red[tid >> 5] = acc;
    __syncthreads();
    if (tid < 8) {
        float v = red[tid];
#pragma unroll
        for (int o = 4; o > 0; o >>= 1) v += __shfl_xor_sync(0xFFu, v, o);
        if (tid == 0) g_x_sq[row] = v;
    }
}

__global__ void psq_kernel(const float* __restrict__ p) {
    int o = blockIdx.x * blockDim.x + threadIdx.x;
    float acc = 0.f;
#pragma unroll 8
    for (int k = 0; k < INDIM; k++) {
        float v = p[(size_t)k * OUTDIM + o];
        acc += v * v;
    }
    g_p_sq[o] = acc;
}

__global__ void transpose_p_kernel(const float* __restrict__ p) {
    __shared__ float tile[32][33];
    int n0 = blockIdx.x * 32;
    int k0 = blockIdx.y * 32;
    int tx = threadIdx.x, ty = threadIdx.y;   // 32 x 8
#pragma unroll
    for (int i = 0; i < 32; i += 8)
        tile[ty + i][tx] = p[(size_t)(k0 + ty + i) * OUTDIM + n0 + tx];
    __syncthreads();
#pragma unroll
    for (int i = 0; i < 32; i += 8)
        g_pt_bf16[(size_t)(n0 + ty + i) * INDIM + k0 + tx] =
            __float2bfloat16(tile[tx][ty + i]);
}

// ---------------- stage loader (256 threads) ----------------
__device__ __forceinline__ void load_stage(uint32_t smem_base, int buf, int m0, int n0,
                                           int k0, int tid) {
    uint32_t a_s = smem_base + SMEM_TILES_OFF + (uint32_t)buf * STAGE_BYTES;
    uint32_t b_s = a_s + BM * 128u;
    const __nv_bfloat16* abase = g_x_bf16 + (size_t)m0 * INDIM + k0;
#pragma unroll
    for (int i = 0; i < (BM * 8) / GEMM_THREADS; i++) {   // 4 chunks/thread
        int idx = tid + i * GEMM_THREADS;
        int r = idx >> 3, c = idx & 7;
        cp_async16(a_s + sw128((uint32_t)(r * 128 + c * 16)),
                   abase + (size_t)r * INDIM + c * 8);
    }
    const __nv_bfloat16* bbase = g_pt_bf16 + (size_t)n0 * INDIM + k0;
#pragma unroll
    for (int i = 0; i < (BN * 8) / GEMM_THREADS; i++) {   // 4 chunks/thread
        int idx = tid + i * GEMM_THREADS;
        int r = idx >> 3, c = idx & 7;
        cp_async16(b_s + sw128((uint32_t)(r * 128 + c * 16)),
                   bbase + (size_t)r * INDIM + c * 8);
    }
}

// ---------------- GEMM: mma.sync bf16 + fused epilogue ----------------
__global__ void __launch_bounds__(GEMM_THREADS, 1)
gemm_kernel(float* __restrict__ out) {
    extern __shared__ char smem[];
    uint32_t smem_base = smem_to_u32(smem);
    const int tid = threadIdx.x;
    const int wid = tid >> 5;
    const int lid = tid & 31;
    const int wm = wid & 3;         // 4 warps along M
    const int wn = wid >> 2;        // 2 warps along N
    const int n0 = blockIdx.x * BN;
    const int m0 = blockIdx.y * BM;

    // stage p_sq tile
    for (int i = tid; i < BN; i += GEMM_THREADS)
        *reinterpret_cast<float*>(smem + SMEM_PSQ_OFF + i * 4) = g_p_sq[n0 + i];

    float acc[2][8][4];
#pragma unroll
    for (int mi = 0; mi < 2; mi++)
#pragma unroll
        for (int nt = 0; nt < 8; nt++)
#pragma unroll
            for (int j = 0; j < 4; j++) acc[mi][nt][j] = 0.f;

    // prologue
#pragma unroll
    for (int s = 0; s < STAGES - 1; s++) {
        load_stage(smem_base, s, m0, n0, s * BK, tid);
        CP_COMMIT();
    }

    // precompute per-lane ldmatrix byte offsets (within tile, unswizzled parts)
    const int a_row = wm * 32 + (lid & 15);          // + mi*16
    const int a_kb  = (lid >> 4) * 16;               // byte offset of k-half
    const int sub   = lid >> 3;
    const int b_row = wn * 64 + (sub >> 1) * 8 + (lid & 7);   // + nj*16
    const int b_kb  = (sub & 1) * 16;

    for (int s = 0; s < NSTAGE_K; s++) {
        __syncthreads();                       // prev compute done before overwrite
        if (s + STAGES - 1 < NSTAGE_K)
            load_stage(smem_base, (s + STAGES - 1) & (STAGES - 1), m0, n0,
                       (s + STAGES - 1) * BK, tid);
        CP_COMMIT();
        CP_WAIT(STAGES - 1);                   // stage s landed (this thread)
        __syncthreads();                       // landed for all threads

        uint32_t a_s = smem_base + SMEM_TILES_OFF + (uint32_t)(s & (STAGES - 1)) * STAGE_BYTES;
        uint32_t b_s = a_s + BM * 128u;

#pragma unroll
        for (int ks = 0; ks < BK / 16; ks++) {
            const int k0b = ks * 32;
            uint32_t afrag[2][4];
#pragma unroll
            for (int mi = 0; mi < 2; mi++) {
                uint32_t off = (uint32_t)((a_row + mi * 16) * 128 + k0b + a_kb);
                ldmatrix_x4(afrag[mi], a_s + sw128(off));
            }
            uint32_t bfrag[8][2];
#pragma unroll
            for (int nj = 0; nj < 4; nj++) {
                uint32_t off = (uint32_t)((b_row + nj * 16) * 128 + k0b + b_kb);
                uint32_t t[4];
                ldmatrix_x4(t, b_s + sw128(off));
                bfrag[nj * 2][0] = t[0]; bfrag[nj * 2][1] = t[1];
                bfrag[nj * 2 + 1][0] = t[2]; bfrag[nj * 2 + 1][1] = t[3];
            }
#pragma unroll
            for (int mi = 0; mi < 2; mi++)
#pragma unroll
                for (int nt = 0; nt < 8; nt++)
                    mma_bf16(acc[mi][nt], afrag[mi], bfrag[nt]);
        }
    }

    // fused epilogue: out = 2*acc - x_sq[m] - p_sq[n]
    const float* psq_s = reinterpret_cast<const float*>(smem + SMEM_PSQ_OFF);
    const int lane4 = lid >> 2;
    const int lane2 = (lid & 3) * 2;
#pragma unroll
    for (int mi = 0; mi < 2; mi++) {
#pragma unroll
        for (int h = 0; h < 2; h++) {
            const int r = m0 + wm * 32 + mi * 16 + lane4 + h * 8;
            const float xs = g_x_sq[r];
            float* orow = out + (size_t)r * OUTDIM + n0 + wn * 64;
#pragma unroll
            for (int nt = 0; nt < 8; nt++) {
                const int cn = nt * 8 + lane2;
                float2 w;
                w.x = 2.0f * acc[mi][nt][h * 2 + 0] - xs - psq_s[wn * 64 + cn];
                w.y = 2.0f * acc[mi][nt][h * 2 + 1] - xs - psq_s[wn * 64 + cn + 1];
                *reinterpret_cast<float2*>(orow + cn) = w;
            }
        }
    }
}

// ---------------- launch ----------------
extern "C" void kernel_launch(void* const* d_in, const int* in_sizes, int n_in,
                              void* d_out, int out_size) {
    const float* x = (const float*)d_in[0];
    const float* p = (const float*)d_in[1];
    if (n_in >= 2 && in_sizes[0] == OUTDIM * INDIM && in_sizes[1] == BATCH * INDIM) {
        x = (const float*)d_in[1];
        p = (const float*)d_in[0];
    }
    float* out = (float*)d_out;

    convert_x_kernel<<<BATCH, 256>>>(x);
    psq_kernel<<<OUTDIM / 256, 256>>>(p);
    transpose_p_kernel<<<dim3(OUTDIM / 32, INDIM / 32), dim3(32, 8)>>>(p);

    cudaFuncSetAttribute(gemm_kernel, cudaFuncAttributeMaxDynamicSharedMemorySize,
                         SMEM_TOTAL);
    gemm_kernel<<<dim3(OUTDIM / BN, BATCH / BM), GEMM_THREADS, SMEM_TOTAL>>>(out);
}

// round 3
// speedup vs baseline: 2.0373x; 2.0373x over previous
#include <cuda_runtime.h>
#include <cuda_bf16.h>
#include <cstdint>
#include <cstddef>

// ---------------- problem constants ----------------
#define INDIM  1024
#define OUTDIM 2048
#define BATCH  8192

#define BM 128
#define BN 128
#define BK 64                    // bf16 elems per stage = 128 B row (swizzle atom)
#define NSTAGE_K (INDIM / BK)    // 16
#define STAGES 4
#define GEMM_THREADS 512

// SMEM: [0,512) p_sq tile, [1024,...) STAGES x (A BM*128B | B BN*128B)
#define SMEM_PSQ_OFF   0u
#define SMEM_TILES_OFF 1024u
#define STAGE_BYTES    ((BM + BN) * 128u)                    // 32768
#define SMEM_TOTAL     (SMEM_TILES_OFF + STAGES * STAGE_BYTES)  // 132096

// ---------------- device scratch (alloc-free) ----------------
__device__ __align__(128) __nv_bfloat16 g_x_bf16[(size_t)BATCH * INDIM];   // 16 MB
__device__ __align__(128) __nv_bfloat16 g_pt_bf16[(size_t)OUTDIM * INDIM]; // 4 MB, [n][k]
__device__ float g_x_sq[BATCH];
__device__ float g_p_sq[OUTDIM];

// ---------------- helpers ----------------
__device__ __forceinline__ uint32_t smem_to_u32(const void* p) {
    uint32_t a;
    asm("{ .reg .u64 t; cvta.to.shared.u64 t, %1; cvt.u32.u64 %0, t; }" : "=r"(a) : "l"(p));
    return a;
}
__device__ __forceinline__ uint32_t sw128(uint32_t off) {
    return off ^ ((off >> 3) & 0x70);
}
__device__ __forceinline__ void cp_async16(uint32_t dst, const void* src) {
    asm volatile("cp.async.cg.shared.global [%0], [%1], 16;" :: "r"(dst), "l"(src) : "memory");
}
#define CP_COMMIT() asm volatile("cp.async.commit_group;" ::: "memory")
#define CP_WAIT(n)  asm volatile("cp.async.wait_group %0;" :: "n"(n) : "memory")

__device__ __forceinline__ void ldmatrix_x4(uint32_t* r, uint32_t addr) {
    asm volatile("ldmatrix.sync.aligned.m8n8.x4.shared.b16 {%0,%1,%2,%3}, [%4];"
                 : "=r"(r[0]), "=r"(r[1]), "=r"(r[2]), "=r"(r[3]) : "r"(addr));
}
__device__ __forceinline__ void mma_bf16(float* c, const uint32_t* a, const uint32_t* b) {
    asm volatile(
        "mma.sync.aligned.m16n8k16.row.col.f32.bf16.bf16.f32 "
        "{%0,%1,%2,%3}, {%4,%5,%6,%7}, {%8,%9}, {%0,%1,%2,%3};"
        : "+f"(c[0]), "+f"(c[1]), "+f"(c[2]), "+f"(c[3])
        : "r"(a[0]), "r"(a[1]), "r"(a[2]), "r"(a[3]), "r"(b[0]), "r"(b[1]));
}

// ---------------- prep kernels ----------------
__global__ void convert_x_kernel(const float* __restrict__ x) {
    int row = blockIdx.x;
    int tid = threadIdx.x;
    const float* xr = x + (size_t)row * INDIM;
    __nv_bfloat16* dst = g_x_bf16 + (size_t)row * INDIM;
    float acc = 0.f;
#pragma unroll
    for (int i = 0; i < INDIM / 256; i++) {
        float v = xr[tid + i * 256];
        acc += v * v;
        dst[tid + i * 256] = __float2bfloat16(v);
    }
#pragma unroll
    for (int o = 16; o > 0; o >>= 1) acc += __shfl_xor_sync(0xFFFFFFFFu, acc, o);
    __shared__ float red[8];
    if ((tid & 31) == 0) red[tid >> 5] = acc;
    __syncthreads();
    if (tid < 8) {
        float v = red[tid];
#pragma unroll
        for (int o = 4; o > 0; o >>= 1) v += __shfl_xor_sync(0xFFu, v, o);
        if (tid == 0) g_x_sq[row] = v;
    }
}

__global__ void zero_psq_kernel() {
    g_p_sq[blockIdx.x * 256 + threadIdx.x] = 0.f;
}

// K split 16 ways across blockIdx.y -> 128 blocks instead of 8.
__global__ void psq_kernel(const float* __restrict__ p) {
    int o = blockIdx.x * 256 + threadIdx.x;
    int k0 = blockIdx.y * (INDIM / 16);
    float acc = 0.f;
#pragma unroll 8
    for (int k = 0; k < INDIM / 16; k++) {
        float v = p[(size_t)(k0 + k) * OUTDIM + o];
        acc += v * v;
    }
    atomicAdd(&g_p_sq[o], acc);
}

__global__ void transpose_p_kernel(const float* __restrict__ p) {
    __shared__ float tile[32][33];
    int n0 = blockIdx.x * 32;
    int k0 = blockIdx.y * 32;
    int tx = threadIdx.x, ty = threadIdx.y;   // 32 x 8
#pragma unroll
    for (int i = 0; i < 32; i += 8)
        tile[ty + i][tx] = p[(size_t)(k0 + ty + i) * OUTDIM + n0 + tx];
    __syncthreads();
#pragma unroll
    for (int i = 0; i < 32; i += 8)
        g_pt_bf16[(size_t)(n0 + ty + i) * INDIM + k0 + tx] =
            __float2bfloat16(tile[tx][ty + i]);
}

// ---------------- stage loader (512 threads) ----------------
__device__ __forceinline__ void load_stage(uint32_t smem_base, int buf, int m0, int n0,
                                           int k0, int tid) {
    uint32_t a_s = smem_base + SMEM_TILES_OFF + (uint32_t)buf * STAGE_BYTES;
    uint32_t b_s = a_s + BM * 128u;
    const __nv_bfloat16* abase = g_x_bf16 + (size_t)m0 * INDIM + k0;
#pragma unroll
    for (int i = 0; i < (BM * 8) / GEMM_THREADS; i++) {   // 2 chunks/thread
        int idx = tid + i * GEMM_THREADS;
        int r = idx >> 3, c = idx & 7;
        cp_async16(a_s + sw128((uint32_t)(r * 128 + c * 16)),
                   abase + (size_t)r * INDIM + c * 8);
    }
    const __nv_bfloat16* bbase = g_pt_bf16 + (size_t)n0 * INDIM + k0;
#pragma unroll
    for (int i = 0; i < (BN * 8) / GEMM_THREADS; i++) {   // 2 chunks/thread
        int idx = tid + i * GEMM_THREADS;
        int r = idx >> 3, c = idx & 7;
        cp_async16(b_s + sw128((uint32_t)(r * 128 + c * 16)),
                   bbase + (size_t)r * INDIM + c * 8);
    }
}

// ---------------- GEMM: mma.sync bf16, 16 warps, fused epilogue ----------------
__global__ void __launch_bounds__(GEMM_THREADS, 1)
gemm_kernel(float* __restrict__ out) {
    extern __shared__ char smem[];
    uint32_t smem_base = smem_to_u32(smem);
    const int tid = threadIdx.x;
    const int wid = tid >> 5;
    const int lid = tid & 31;
    const int wm = wid & 3;         // 4 warps along M (32 rows each)
    const int wn = wid >> 2;        // 4 warps along N (32 cols each)
    const int n0 = blockIdx.x * BN;
    const int m0 = blockIdx.y * BM;

    // stage p_sq tile
    for (int i = tid; i < BN; i += GEMM_THREADS)
        *reinterpret_cast<float*>(smem + SMEM_PSQ_OFF + i * 4) = g_p_sq[n0 + i];

    float acc[2][4][4];
#pragma unroll
    for (int mi = 0; mi < 2; mi++)
#pragma unroll
        for (int nt = 0; nt < 4; nt++)
#pragma unroll
            for (int j = 0; j < 4; j++) acc[mi][nt][j] = 0.f;

    // prologue: stages 0..2
#pragma unroll
    for (int s = 0; s < STAGES - 1; s++) {
        load_stage(smem_base, s, m0, n0, s * BK, tid);
        CP_COMMIT();
    }

    // per-lane ldmatrix row/offset components
    const int a_row = wm * 32 + (lid & 15);                   // + mi*16
    const int a_kb  = (lid >> 4) * 16;
    const int sub   = lid >> 3;
    const int b_row = wn * 32 + (sub >> 1) * 8 + (lid & 7);   // + nj*16
    const int b_kb  = (sub & 1) * 16;

    for (int s = 0; s < NSTAGE_K; s++) {
        CP_WAIT(STAGES - 2);                   // stage s landed (this thread)
        __syncthreads();                       // landed for all; all finished compute(s-1)
        if (s + STAGES - 1 < NSTAGE_K)
            load_stage(smem_base, (s + STAGES - 1) & (STAGES - 1), m0, n0,
                       (s + STAGES - 1) * BK, tid);
        CP_COMMIT();                           // empty group when no loads

        uint32_t a_s = smem_base + SMEM_TILES_OFF + (uint32_t)(s & (STAGES - 1)) * STAGE_BYTES;
        uint32_t b_s = a_s + BM * 128u;

#pragma unroll
        for (int ks = 0; ks < BK / 16; ks++) {
            const int k0b = ks * 32;
            uint32_t afrag[2][4];
#pragma unroll
            for (int mi = 0; mi < 2; mi++) {
                uint32_t off = (uint32_t)((a_row + mi * 16) * 128 + k0b + a_kb);
                ldmatrix_x4(afrag[mi], a_s + sw128(off));
            }
            uint32_t bfrag[4][2];
#pragma unroll
            for (int nj = 0; nj < 2; nj++) {
                uint32_t off = (uint32_t)((b_row + nj * 16) * 128 + k0b + b_kb);
                uint32_t t[4];
                ldmatrix_x4(t, b_s + sw128(off));
                bfrag[nj * 2][0] = t[0]; bfrag[nj * 2][1] = t[1];
                bfrag[nj * 2 + 1][0] = t[2]; bfrag[nj * 2 + 1][1] = t[3];
            }
#pragma unroll
            for (int mi = 0; mi < 2; mi++)
#pragma unroll
                for (int nt = 0; nt < 4; nt++)
                    mma_bf16(acc[mi][nt], afrag[mi], bfrag[nt]);
        }
    }

    // fused epilogue: out = 2*acc - x_sq[m] - p_sq[n]
    const float* psq_s = reinterpret_cast<const float*>(smem + SMEM_PSQ_OFF);
    const int lane4 = lid >> 2;
    const int lane2 = (lid & 3) * 2;
#pragma unroll
    for (int mi = 0; mi < 2; mi++) {
#pragma unroll
        for (int h = 0; h < 2; h++) {
            const int r = m0 + wm * 32 + mi * 16 + lane4 + h * 8;
            const float xs = g_x_sq[r];
            float* orow = out + (size_t)r * OUTDIM + n0 + wn * 32;
#pragma unroll
            for (int nt = 0; nt < 4; nt++) {
                const int cn = nt * 8 + lane2;
                float2 w;
                w.x = 2.0f * acc[mi][nt][h * 2 + 0] - xs - psq_s[wn * 32 + cn];
                w.y = 2.0f * acc[mi][nt][h * 2 + 1] - xs - psq_s[wn * 32 + cn + 1];
                *reinterpret_cast<float2*>(orow + cn) = w;
            }
        }
    }
}

// ---------------- launch ----------------
extern "C" void kernel_launch(void* const* d_in, const int* in_sizes, int n_in,
                              void* d_out, int out_size) {
    const float* x = (const float*)d_in[0];
    const float* p = (const float*)d_in[1];
    if (n_in >= 2 && in_sizes[0] == OUTDIM * INDIM && in_sizes[1] == BATCH * INDIM) {
        x = (const float*)d_in[1];
        p = (const float*)d_in[0];
    }
    float* out = (float*)d_out;

    convert_x_kernel<<<BATCH, 256>>>(x);
    zero_psq_kernel<<<OUTDIM / 256, 256>>>();
    psq_kernel<<<dim3(OUTDIM / 256, 16), 256>>>(p);
    transpose_p_kernel<<<dim3(OUTDIM / 32, INDIM / 32), dim3(32, 8)>>>(p);

    cudaFuncSetAttribute(gemm_kernel, cudaFuncAttributeMaxDynamicSharedMemorySize,
                         SMEM_TOTAL);
    gemm_kernel<<<dim3(OUTDIM / BN, BATCH / BM), GEMM_THREADS, SMEM_TOTAL>>>(out);
}

// round 4
// speedup vs baseline: 2.1673x; 1.0638x over previous
#include <cuda_runtime.h>
#include <cuda_bf16.h>
#include <cuda_fp8.h>
#include <cstdint>
#include <cstddef>

// ---------------- problem constants ----------------
#define INDIM  1024
#define OUTDIM 2048
#define BATCH  8192

#define BM 128
#define BN 128
#define BK 128                   // fp8 elems per stage = 128 B row (swizzle atom)
#define NSTAGE_K (INDIM / BK)    // 8
#define STAGES 4
#define GEMM_THREADS 512

// P is scaled by 32 before fp8 quantization; epilogue multiplies acc by 2/32.
#define ACC_SCALE 0.0625f

// SMEM: [0,512) p_sq tile, [1024,...) STAGES x (A BM*128B | B BN*128B)
#define SMEM_PSQ_OFF   0u
#define SMEM_TILES_OFF 1024u
#define STAGE_BYTES    ((BM + BN) * 128u)                    // 32768
#define SMEM_TOTAL     (SMEM_TILES_OFF + STAGES * STAGE_BYTES)  // 132096

// ---------------- device scratch (alloc-free) ----------------
__device__ __align__(128) uint8_t g_x_fp8[(size_t)BATCH * INDIM];   // 8 MB, e4m3
__device__ __align__(128) uint8_t g_pt_fp8[(size_t)OUTDIM * INDIM]; // 2 MB, [n][k], e4m3 of 32*p
__device__ float g_x_sq[BATCH];
__device__ float g_p_sq[OUTDIM];

// ---------------- helpers ----------------
__device__ __forceinline__ uint32_t smem_to_u32(const void* p) {
    uint32_t a;
    asm("{ .reg .u64 t; cvta.to.shared.u64 t, %1; cvt.u32.u64 %0, t; }" : "=r"(a) : "l"(p));
    return a;
}
__device__ __forceinline__ uint32_t sw128(uint32_t off) {
    return off ^ ((off >> 3) & 0x70);
}
__device__ __forceinline__ void cp_async16(uint32_t dst, const void* src) {
    asm volatile("cp.async.cg.shared.global [%0], [%1], 16;" :: "r"(dst), "l"(src) : "memory");
}
#define CP_COMMIT() asm volatile("cp.async.commit_group;" ::: "memory")
#define CP_WAIT(n)  asm volatile("cp.async.wait_group %0;" :: "n"(n) : "memory")

__device__ __forceinline__ void ldmatrix_x4(uint32_t* r, uint32_t addr) {
    asm volatile("ldmatrix.sync.aligned.m8n8.x4.shared.b16 {%0,%1,%2,%3}, [%4];"
                 : "=r"(r[0]), "=r"(r[1]), "=r"(r[2]), "=r"(r[3]) : "r"(addr));
}
// fp8 e4m3 MMA, fp32 accum. Fragment byte-layout identical to bf16 m16n8k16 case.
__device__ __forceinline__ void mma_fp8(float* c, const uint32_t* a, const uint32_t* b) {
    asm volatile(
        "mma.sync.aligned.m16n8k32.row.col.f32.e4m3.e4m3.f32 "
        "{%0,%1,%2,%3}, {%4,%5,%6,%7}, {%8,%9}, {%0,%1,%2,%3};"
        : "+f"(c[0]), "+f"(c[1]), "+f"(c[2]), "+f"(c[3])
        : "r"(a[0]), "r"(a[1]), "r"(a[2]), "r"(a[3]), "r"(b[0]), "r"(b[1]));
}

__device__ __forceinline__ uint8_t to_e4m3(float v) {
    return (uint8_t)__nv_cvt_float_to_fp8(v, __NV_SATFINITE, __NV_E4M3);
}

// ---------------- prep kernels ----------------
__global__ void convert_x_kernel(const float* __restrict__ x) {
    int row = blockIdx.x;
    int tid = threadIdx.x;
    const float* xr = x + (size_t)row * INDIM;
    uint8_t* dst = g_x_fp8 + (size_t)row * INDIM;
    float acc = 0.f;
#pragma unroll
    for (int i = 0; i < INDIM / 256; i++) {
        float v = xr[tid + i * 256];
        acc += v * v;
        dst[tid + i * 256] = to_e4m3(v);
    }
#pragma unroll
    for (int o = 16; o > 0; o >>= 1) acc += __shfl_xor_sync(0xFFFFFFFFu, acc, o);
    __shared__ float red[8];
    if ((tid & 31) == 0) red[tid >> 5] = acc;
    __syncthreads();
    if (tid < 8) {
        float v = red[tid];
#pragma unroll
        for (int o = 4; o > 0; o >>= 1) v += __shfl_xor_sync(0xFFu, v, o);
        if (tid == 0) g_x_sq[row] = v;
    }
}

__global__ void zero_psq_kernel() {
    g_p_sq[blockIdx.x * 256 + threadIdx.x] = 0.f;
}

__global__ void psq_kernel(const float* __restrict__ p) {
    int o = blockIdx.x * 256 + threadIdx.x;
    int k0 = blockIdx.y * (INDIM / 16);
    float acc = 0.f;
#pragma unroll 8
    for (int k = 0; k < INDIM / 16; k++) {
        float v = p[(size_t)(k0 + k) * OUTDIM + o];
        acc += v * v;
    }
    atomicAdd(&g_p_sq[o], acc);
}

__global__ void transpose_p_kernel(const float* __restrict__ p) {
    __shared__ float tile[32][33];
    int n0 = blockIdx.x * 32;
    int k0 = blockIdx.y * 32;
    int tx = threadIdx.x, ty = threadIdx.y;   // 32 x 8
#pragma unroll
    for (int i = 0; i < 32; i += 8)
        tile[ty + i][tx] = p[(size_t)(k0 + ty + i) * OUTDIM + n0 + tx];
    __syncthreads();
#pragma unroll
    for (int i = 0; i < 32; i += 8)
        g_pt_fp8[(size_t)(n0 + ty + i) * INDIM + k0 + tx] =
            to_e4m3(32.0f * tile[tx][ty + i]);
}

// ---------------- stage loader (512 threads) ----------------
__device__ __forceinline__ void load_stage(uint32_t smem_base, int buf, int m0, int n0,
                                           int k0, int tid) {
    uint32_t a_s = smem_base + SMEM_TILES_OFF + (uint32_t)buf * STAGE_BYTES;
    uint32_t b_s = a_s + BM * 128u;
    const uint8_t* abase = g_x_fp8 + (size_t)m0 * INDIM + k0;
#pragma unroll
    for (int i = 0; i < (BM * 8) / GEMM_THREADS; i++) {   // 2 chunks/thread
        int idx = tid + i * GEMM_THREADS;
        int r = idx >> 3, c = idx & 7;
        cp_async16(a_s + sw128((uint32_t)(r * 128 + c * 16)),
                   abase + (size_t)r * INDIM + c * 16);
    }
    const uint8_t* bbase = g_pt_fp8 + (size_t)n0 * INDIM + k0;
#pragma unroll
    for (int i = 0; i < (BN * 8) / GEMM_THREADS; i++) {   // 2 chunks/thread
        int idx = tid + i * GEMM_THREADS;
        int r = idx >> 3, c = idx & 7;
        cp_async16(b_s + sw128((uint32_t)(r * 128 + c * 16)),
                   bbase + (size_t)r * INDIM + c * 16);
    }
}

// ---------------- GEMM: mma.sync fp8, 16 warps, fused epilogue ----------------
__global__ void __launch_bounds__(GEMM_THREADS, 1)
gemm_kernel(float* __restrict__ out) {
    extern __shared__ char smem[];
    uint32_t smem_base = smem_to_u32(smem);
    const int tid = threadIdx.x;
    const int wid = tid >> 5;
    const int lid = tid & 31;
    const int wm = wid & 3;         // 4 warps along M (32 rows each)
    const int wn = wid >> 2;        // 4 warps along N (32 cols each)
    const int n0 = blockIdx.x * BN;
    const int m0 = blockIdx.y * BM;

    // stage p_sq tile
    for (int i = tid; i < BN; i += GEMM_THREADS)
        *reinterpret_cast<float*>(smem + SMEM_PSQ_OFF + i * 4) = g_p_sq[n0 + i];

    float acc[2][4][4];
#pragma unroll
    for (int mi = 0; mi < 2; mi++)
#pragma unroll
        for (int nt = 0; nt < 4; nt++)
#pragma unroll
            for (int j = 0; j < 4; j++) acc[mi][nt][j] = 0.f;

    // prologue: stages 0..2
#pragma unroll
    for (int s = 0; s < STAGES - 1; s++) {
        load_stage(smem_base, s, m0, n0, s * BK, tid);
        CP_COMMIT();
    }

    // per-lane ldmatrix row/offset components (byte-identical to bf16 case)
    const int a_row = wm * 32 + (lid & 15);                   // + mi*16
    const int a_kb  = (lid >> 4) * 16;
    const int sub   = lid >> 3;
    const int b_row = wn * 32 + (sub >> 1) * 8 + (lid & 7);   // + nj*16
    const int b_kb  = (sub & 1) * 16;

    for (int s = 0; s < NSTAGE_K; s++) {
        CP_WAIT(STAGES - 2);                   // stage s landed (this thread)
        __syncthreads();                       // landed for all; all finished compute(s-1)
        if (s + STAGES - 1 < NSTAGE_K)
            load_stage(smem_base, (s + STAGES - 1) & (STAGES - 1), m0, n0,
                       (s + STAGES - 1) * BK, tid);
        CP_COMMIT();                           // empty group when no loads

        uint32_t a_s = smem_base + SMEM_TILES_OFF + (uint32_t)(s & (STAGES - 1)) * STAGE_BYTES;
        uint32_t b_s = a_s + BM * 128u;

#pragma unroll
        for (int ks = 0; ks < BK / 32; ks++) { // 4 k-chunks of 32 fp8 = 32 bytes
            const int k0b = ks * 32;
            uint32_t afrag[2][4];
#pragma unroll
            for (int mi = 0; mi < 2; mi++) {
                uint32_t off = (uint32_t)((a_row + mi * 16) * 128 + k0b + a_kb);
                ldmatrix_x4(afrag[mi], a_s + sw128(off));
            }
            uint32_t bfrag[4][2];
#pragma unroll
            for (int nj = 0; nj < 2; nj++) {
                uint32_t off = (uint32_t)((b_row + nj * 16) * 128 + k0b + b_kb);
                uint32_t t[4];
                ldmatrix_x4(t, b_s + sw128(off));
                bfrag[nj * 2][0] = t[0]; bfrag[nj * 2][1] = t[1];
                bfrag[nj * 2 + 1][0] = t[2]; bfrag[nj * 2 + 1][1] = t[3];
            }
#pragma unroll
            for (int mi = 0; mi < 2; mi++)
#pragma unroll
                for (int nt = 0; nt < 4; nt++)
                    mma_fp8(acc[mi][nt], afrag[mi], bfrag[nt]);
        }
    }

    // fused epilogue: out = (2/32)*acc - x_sq[m] - p_sq[n]
    const float* psq_s = reinterpret_cast<const float*>(smem + SMEM_PSQ_OFF);
    const int lane4 = lid >> 2;
    const int lane2 = (lid & 3) * 2;
#pragma unroll
    for (int mi = 0; mi < 2; mi++) {
#pragma unroll
        for (int h = 0; h < 2; h++) {
            const int r = m0 + wm * 32 + mi * 16 + lane4 + h * 8;
            const float xs = g_x_sq[r];
            float* orow = out + (size_t)r * OUTDIM + n0 + wn * 32;
#pragma unroll
            for (int nt = 0; nt < 4; nt++) {
                const int cn = nt * 8 + lane2;
                float2 w;
                w.x = fmaf(ACC_SCALE, acc[mi][nt][h * 2 + 0], -xs - psq_s[wn * 32 + cn]);
                w.y = fmaf(ACC_SCALE, acc[mi][nt][h * 2 + 1], -xs - psq_s[wn * 32 + cn + 1]);
                *reinterpret_cast<float2*>(orow + cn) = w;
            }
        }
    }
}

// ---------------- launch ----------------
extern "C" void kernel_launch(void* const* d_in, const int* in_sizes, int n_in,
                              void* d_out, int out_size) {
    const float* x = (const float*)d_in[0];
    const float* p = (const float*)d_in[1];
    if (n_in >= 2 && in_sizes[0] == OUTDIM * INDIM && in_sizes[1] == BATCH * INDIM) {
        x = (const float*)d_in[1];
        p = (const float*)d_in[0];
    }
    float* out = (float*)d_out;

    convert_x_kernel<<<BATCH, 256>>>(x);
    zero_psq_kernel<<<OUTDIM / 256, 256>>>();
    psq_kernel<<<dim3(OUTDIM / 256, 16), 256>>>(p);
    transpose_p_kernel<<<dim3(OUTDIM / 32, INDIM / 32), dim3(32, 8)>>>(p);

    cudaFuncSetAttribute(gemm_kernel, cudaFuncAttributeMaxDynamicSharedMemorySize,
                         SMEM_TOTAL);
    gemm_kernel<<<dim3(OUTDIM / BN, BATCH / BM), GEMM_THREADS, SMEM_TOTAL>>>(out);
}

// round 5
// speedup vs baseline: 2.2783x; 1.0512x over previous
#include <cuda_runtime.h>
#include <cuda_bf16.h>
#include <cuda_fp8.h>
#include <cstdint>
#include <cstddef>

// ---------------- problem constants ----------------
#define INDIM  1024
#define OUTDIM 2048
#define BATCH  8192

#define BM 128
#define BN 128
#define BK 128                   // fp8 elems per stage = 128 B row (swizzle atom)
#define NSTAGE_K (INDIM / BK)    // 8
#define STAGES 3
#define GEMM_THREADS 256

// P is scaled by 32 before fp8 quantization; epilogue multiplies acc by 2/32.
#define ACC_SCALE 0.0625f

// SMEM: [0,512) p_sq tile, [1024,...) STAGES x (A BM*128B | B BN*128B)
#define SMEM_PSQ_OFF   0u
#define SMEM_TILES_OFF 1024u
#define STAGE_BYTES    ((BM + BN) * 128u)                       // 32768
#define SMEM_TOTAL     (SMEM_TILES_OFF + STAGES * STAGE_BYTES)  // 99328 (x2 CTAs = 194KB/SM)

// ---------------- device scratch (alloc-free) ----------------
__device__ __align__(128) uint8_t g_x_fp8[(size_t)BATCH * INDIM];   // 8 MB, e4m3
__device__ __align__(128) uint8_t g_pt_fp8[(size_t)OUTDIM * INDIM]; // 2 MB, [n][k], e4m3 of 32*p
__device__ float g_x_sq[BATCH];
__device__ float g_p_sq[OUTDIM];

// ---------------- helpers ----------------
__device__ __forceinline__ uint32_t smem_to_u32(const void* p) {
    uint32_t a;
    asm("{ .reg .u64 t; cvta.to.shared.u64 t, %1; cvt.u32.u64 %0, t; }" : "=r"(a) : "l"(p));
    return a;
}
__device__ __forceinline__ uint32_t sw128(uint32_t off) {
    return off ^ ((off >> 3) & 0x70);
}
__device__ __forceinline__ void cp_async16(uint32_t dst, const void* src) {
    asm volatile("cp.async.cg.shared.global [%0], [%1], 16;" :: "r"(dst), "l"(src) : "memory");
}
#define CP_COMMIT() asm volatile("cp.async.commit_group;" ::: "memory")
#define CP_WAIT(n)  asm volatile("cp.async.wait_group %0;" :: "n"(n) : "memory")

__device__ __forceinline__ void ldmatrix_x4(uint32_t* r, uint32_t addr) {
    asm volatile("ldmatrix.sync.aligned.m8n8.x4.shared.b16 {%0,%1,%2,%3}, [%4];"
                 : "=r"(r[0]), "=r"(r[1]), "=r"(r[2]), "=r"(r[3]) : "r"(addr));
}
__device__ __forceinline__ void mma_fp8(float* c, const uint32_t* a, const uint32_t* b) {
    asm volatile(
        "mma.sync.aligned.m16n8k32.row.col.f32.e4m3.e4m3.f32 "
        "{%0,%1,%2,%3}, {%4,%5,%6,%7}, {%8,%9}, {%0,%1,%2,%3};"
        : "+f"(c[0]), "+f"(c[1]), "+f"(c[2]), "+f"(c[3])
        : "r"(a[0]), "r"(a[1]), "r"(a[2]), "r"(a[3]), "r"(b[0]), "r"(b[1]));
}

__device__ __forceinline__ uint8_t to_e4m3(float v) {
    return (uint8_t)__nv_cvt_float_to_fp8(v, __NV_SATFINITE, __NV_E4M3);
}

// ---------------- prep kernels ----------------
// Converts x to fp8, computes row norms, and zeroes g_p_sq (blocks 0..7).
__global__ void convert_x_kernel(const float* __restrict__ x) {
    int row = blockIdx.x;
    int tid = threadIdx.x;
    if (row < OUTDIM / 256) g_p_sq[row * 256 + tid] = 0.f;
    const float* xr = x + (size_t)row * INDIM;
    uint8_t* dst = g_x_fp8 + (size_t)row * INDIM;
    float acc = 0.f;
#pragma unroll
    for (int i = 0; i < INDIM / 256; i++) {
        float v = xr[tid + i * 256];
        acc += v * v;
        dst[tid + i * 256] = to_e4m3(v);
    }
#pragma unroll
    for (int o = 16; o > 0; o >>= 1) acc += __shfl_xor_sync(0xFFFFFFFFu, acc, o);
    __shared__ float red[8];
    if ((tid & 31) == 0) red[tid >> 5] = acc;
    __syncthreads();
    if (tid < 8) {
        float v = red[tid];
#pragma unroll
        for (int o = 4; o > 0; o >>= 1) v += __shfl_xor_sync(0xFFu, v, o);
        if (tid == 0) g_x_sq[row] = v;
    }
}

// Fused: transpose+quantize P to fp8 [n][k] AND accumulate column norms p_sq.
__global__ void transpose_psq_kernel(const float* __restrict__ p) {
    __shared__ float tile[32][33];     // tile[k_local][n_local]
    __shared__ float partial[8][33];
    int n0 = blockIdx.x * 32;
    int k0 = blockIdx.y * 32;
    int tx = threadIdx.x, ty = threadIdx.y;   // 32 x 8
    float sq = 0.f;
#pragma unroll
    for (int i = 0; i < 32; i += 8) {
        float v = p[(size_t)(k0 + ty + i) * OUTDIM + n0 + tx];
        tile[ty + i][tx] = v;
    }
    __syncthreads();
    // partial column sums: thread (tx,ty) sums k = ty, ty+8, ty+16, ty+24 for n=tx
#pragma unroll
    for (int i = 0; i < 4; i++) {
        float v = tile[ty + i * 8][tx];
        sq += v * v;
    }
    partial[ty][tx] = sq;
    // transposed fp8 write (32*p)
#pragma unroll
    for (int i = 0; i < 32; i += 8)
        g_pt_fp8[(size_t)(n0 + ty + i) * INDIM + k0 + tx] =
            to_e4m3(32.0f * tile[tx][ty + i]);
    __syncthreads();
    if (ty == 0) {
        float s = 0.f;
#pragma unroll
        for (int j = 0; j < 8; j++) s += partial[j][tx];
        atomicAdd(&g_p_sq[n0 + tx], s);
    }
}

// ---------------- stage loader (256 threads) ----------------
__device__ __forceinline__ void load_stage(uint32_t smem_base, int buf, int m0, int n0,
                                           int k0, int tid) {
    uint32_t a_s = smem_base + SMEM_TILES_OFF + (uint32_t)buf * STAGE_BYTES;
    uint32_t b_s = a_s + BM * 128u;
    const uint8_t* abase = g_x_fp8 + (size_t)m0 * INDIM + k0;
#pragma unroll
    for (int i = 0; i < (BM * 8) / GEMM_THREADS; i++) {   // 4 chunks/thread
        int idx = tid + i * GEMM_THREADS;
        int r = idx >> 3, c = idx & 7;
        cp_async16(a_s + sw128((uint32_t)(r * 128 + c * 16)),
                   abase + (size_t)r * INDIM + c * 16);
    }
    const uint8_t* bbase = g_pt_fp8 + (size_t)n0 * INDIM + k0;
#pragma unroll
    for (int i = 0; i < (BN * 8) / GEMM_THREADS; i++) {   // 4 chunks/thread
        int idx = tid + i * GEMM_THREADS;
        int r = idx >> 3, c = idx & 7;
        cp_async16(b_s + sw128((uint32_t)(r * 128 + c * 16)),
                   bbase + (size_t)r * INDIM + c * 16);
    }
}

// ---------------- GEMM: mma.sync fp8, 8 warps x (32x64), 2 CTAs/SM ----------------
__global__ void __launch_bounds__(GEMM_THREADS, 2)
gemm_kernel(float* __restrict__ out) {
    extern __shared__ char smem[];
    uint32_t smem_base = smem_to_u32(smem);
    const int tid = threadIdx.x;
    const int wid = tid >> 5;
    const int lid = tid & 31;
    const int wm = wid & 3;         // 4 warps along M (32 rows each)
    const int wn = wid >> 2;        // 2 warps along N (64 cols each)
    const int n0 = blockIdx.x * BN;
    const int m0 = blockIdx.y * BM;

    // stage p_sq tile
    for (int i = tid; i < BN; i += GEMM_THREADS)
        *reinterpret_cast<float*>(smem + SMEM_PSQ_OFF + i * 4) = g_p_sq[n0 + i];

    float acc[2][8][4];
#pragma unroll
    for (int mi = 0; mi < 2; mi++)
#pragma unroll
        for (int nt = 0; nt < 8; nt++)
#pragma unroll
            for (int j = 0; j < 4; j++) acc[mi][nt][j] = 0.f;

    // prologue: stages 0..1
#pragma unroll
    for (int s = 0; s < STAGES - 1; s++) {
        load_stage(smem_base, s, m0, n0, s * BK, tid);
        CP_COMMIT();
    }

    // per-lane ldmatrix row/offset components
    const int a_row = wm * 32 + (lid & 15);                   // + mi*16
    const int a_kb  = (lid >> 4) * 16;
    const int sub   = lid >> 3;
    const int b_row = wn * 64 + (sub >> 1) * 8 + (lid & 7);   // + nj*16
    const int b_kb  = (sub & 1) * 16;

    int buf = 0;
    for (int s = 0; s < NSTAGE_K; s++) {
        CP_WAIT(STAGES - 2);                   // stage s landed (this thread)
        __syncthreads();                       // landed for all; all finished compute(s-1)
        if (s + STAGES - 1 < NSTAGE_K)
            load_stage(smem_base, (buf + STAGES - 1) % STAGES, m0, n0,
                       (s + STAGES - 1) * BK, tid);
        CP_COMMIT();                           // empty group when no loads

        uint32_t a_s = smem_base + SMEM_TILES_OFF + (uint32_t)buf * STAGE_BYTES;
        uint32_t b_s = a_s + BM * 128u;

#pragma unroll
        for (int ks = 0; ks < BK / 32; ks++) { // 4 k-chunks of 32 bytes
            const int k0b = ks * 32;
            uint32_t afrag[2][4];
#pragma unroll
            for (int mi = 0; mi < 2; mi++) {
                uint32_t off = (uint32_t)((a_row + mi * 16) * 128 + k0b + a_kb);
                ldmatrix_x4(afrag[mi], a_s + sw128(off));
            }
            // process B in two halves of 4 n-tiles to cap register pressure
#pragma unroll
            for (int half = 0; half < 2; half++) {
                uint32_t bfrag[4][2];
#pragma unroll
                for (int nj = 0; nj < 2; nj++) {
                    uint32_t off = (uint32_t)((b_row + (half * 2 + nj) * 16) * 128 + k0b + b_kb);
                    uint32_t t[4];
                    ldmatrix_x4(t, b_s + sw128(off));
                    bfrag[nj * 2][0] = t[0]; bfrag[nj * 2][1] = t[1];
                    bfrag[nj * 2 + 1][0] = t[2]; bfrag[nj * 2 + 1][1] = t[3];
                }
#pragma unroll
                for (int mi = 0; mi < 2; mi++)
#pragma unroll
                    for (int nt = 0; nt < 4; nt++)
                        mma_fp8(acc[mi][half * 4 + nt], afrag[mi], bfrag[nt]);
            }
        }
        buf = (buf + 1 == STAGES) ? 0 : buf + 1;
    }

    // fused epilogue: out = (2/32)*acc - x_sq[m] - p_sq[n]
    const float* psq_s = reinterpret_cast<const float*>(smem + SMEM_PSQ_OFF);
    const int lane4 = lid >> 2;
    const int lane2 = (lid & 3) * 2;
#pragma unroll
    for (int mi = 0; mi < 2; mi++) {
#pragma unroll
        for (int h = 0; h < 2; h++) {
            const int r = m0 + wm * 32 + mi * 16 + lane4 + h * 8;
            const float xs = g_x_sq[r];
            float* orow = out + (size_t)r * OUTDIM + n0 + wn * 64;
#pragma unroll
            for (int nt = 0; nt < 8; nt++) {
                const int cn = nt * 8 + lane2;
                float2 w;
                w.x = fmaf(ACC_SCALE, acc[mi][nt][h * 2 + 0], -xs - psq_s[wn * 64 + cn]);
                w.y = fmaf(ACC_SCALE, acc[mi][nt][h * 2 + 1], -xs - psq_s[wn * 64 + cn + 1]);
                *reinterpret_cast<float2*>(orow + cn) = w;
            }
        }
    }
}

// ---------------- launch ----------------
extern "C" void kernel_launch(void* const* d_in, const int* in_sizes, int n_in,
                              void* d_out, int out_size) {
    const float* x = (const float*)d_in[0];
    const float* p = (const float*)d_in[1];
    if (n_in >= 2 && in_sizes[0] == OUTDIM * INDIM && in_sizes[1] == BATCH * INDIM) {
        x = (const float*)d_in[1];
        p = (const float*)d_in[0];
    }
    float* out = (float*)d_out;

    convert_x_kernel<<<BATCH, 256>>>(x);             // also zeroes g_p_sq
    transpose_psq_kernel<<<dim3(OUTDIM / 32, INDIM / 32), dim3(32, 8)>>>(p);

    cudaFuncSetAttribute(gemm_kernel, cudaFuncAttributeMaxDynamicSharedMemorySize,
                         SMEM_TOTAL);
    gemm_kernel<<<dim3(OUTDIM / BN, BATCH / BM), GEMM_THREADS, SMEM_TOTAL>>>(out);
}

// round 6
// speedup vs baseline: 2.6127x; 1.1468x over previous
#include <cuda_runtime.h>
#include <cuda_bf16.h>
#include <cuda_fp16.h>
#include <cuda_fp8.h>
#include <cstdint>
#include <cstddef>

// ---------------- problem constants ----------------
#define INDIM  1024
#define OUTDIM 2048
#define BATCH  8192

#define BM 128
#define BN 128
#define BK 128                   // fp8 elems per stage = 128 B row (swizzle atom)
#define NSTAGE_K (INDIM / BK)    // 8
#define STAGES 3
#define GEMM_THREADS 256

// P is scaled by 32 before fp8 quantization; epilogue multiplies acc by 2/32.
#define ACC_SCALE 0.0625f

// SMEM: [0,512) p_sq tile, [1024,...) STAGES x (A BM*128B | B BN*128B)
#define SMEM_PSQ_OFF   0u
#define SMEM_TILES_OFF 1024u
#define STAGE_BYTES    ((BM + BN) * 128u)                       // 32768
#define SMEM_TOTAL     (SMEM_TILES_OFF + STAGES * STAGE_BYTES)  // 99328 (x2 CTAs = 194KB/SM)

// ---------------- device scratch (alloc-free) ----------------
__device__ __align__(128) uint8_t g_x_fp8[(size_t)BATCH * INDIM];   // 8 MB, e4m3
__device__ __align__(128) uint8_t g_pt_fp8[(size_t)OUTDIM * INDIM]; // 2 MB, [n][k], e4m3 of 32*p
__device__ float g_x_sq[BATCH];
__device__ float g_p_sq[OUTDIM];

// ---------------- helpers ----------------
__device__ __forceinline__ uint32_t smem_to_u32(const void* p) {
    uint32_t a;
    asm("{ .reg .u64 t; cvta.to.shared.u64 t, %1; cvt.u32.u64 %0, t; }" : "=r"(a) : "l"(p));
    return a;
}
__device__ __forceinline__ uint32_t sw128(uint32_t off) {
    return off ^ ((off >> 3) & 0x70);
}
__device__ __forceinline__ void cp_async16(uint32_t dst, const void* src) {
    asm volatile("cp.async.cg.shared.global [%0], [%1], 16;" :: "r"(dst), "l"(src) : "memory");
}
#define CP_COMMIT() asm volatile("cp.async.commit_group;" ::: "memory")
#define CP_WAIT(n)  asm volatile("cp.async.wait_group %0;" :: "n"(n) : "memory")

__device__ __forceinline__ void ldmatrix_x4(uint32_t* r, uint32_t addr) {
    asm volatile("ldmatrix.sync.aligned.m8n8.x4.shared.b16 {%0,%1,%2,%3}, [%4];"
                 : "=r"(r[0]), "=r"(r[1]), "=r"(r[2]), "=r"(r[3]) : "r"(addr));
}
// fp8 e4m3 MMA with fp16 accumulator (2 packed f16x2 regs).
__device__ __forceinline__ void mma_fp8_h(uint32_t* c, const uint32_t* a, const uint32_t* b) {
    asm volatile(
        "mma.sync.aligned.m16n8k32.row.col.f16.e4m3.e4m3.f16 "
        "{%0,%1}, {%2,%3,%4,%5}, {%6,%7}, {%0,%1};"
        : "+r"(c[0]), "+r"(c[1])
        : "r"(a[0]), "r"(a[1]), "r"(a[2]), "r"(a[3]), "r"(b[0]), "r"(b[1]));
}

__device__ __forceinline__ uint8_t to_e4m3(float v) {
    return (uint8_t)__nv_cvt_float_to_fp8(v, __NV_SATFINITE, __NV_E4M3);
}

// ---------------- prep kernels ----------------
// Vectorized: converts x to fp8 (float4 in, uchar4 out), row norms, zeroes g_p_sq.
__global__ void convert_x_kernel(const float* __restrict__ x) {
    int row = blockIdx.x;
    int tid = threadIdx.x;
    if (row < OUTDIM / 256) g_p_sq[row * 256 + tid] = 0.f;
    const float4* xr = reinterpret_cast<const float4*>(x + (size_t)row * INDIM);
    uchar4* dst = reinterpret_cast<uchar4*>(g_x_fp8 + (size_t)row * INDIM);
    float4 v = xr[tid];
    float acc = v.x * v.x + v.y * v.y + v.z * v.z + v.w * v.w;
    uchar4 q;
    q.x = to_e4m3(v.x); q.y = to_e4m3(v.y); q.z = to_e4m3(v.z); q.w = to_e4m3(v.w);
    dst[tid] = q;
#pragma unroll
    for (int o = 16; o > 0; o >>= 1) acc += __shfl_xor_sync(0xFFFFFFFFu, acc, o);
    __shared__ float red[8];
    if ((tid & 31) == 0) red[tid >> 5] = acc;
    __syncthreads();
    if (tid < 8) {
        float s = red[tid];
#pragma unroll
        for (int o = 4; o > 0; o >>= 1) s += __shfl_xor_sync(0xFFu, s, o);
        if (tid == 0) g_x_sq[row] = s;
    }
}

// Fused: transpose+quantize P to fp8 [n][k] AND accumulate column norms p_sq.
__global__ void transpose_psq_kernel(const float* __restrict__ p) {
    __shared__ float tile[32][33];     // tile[k_local][n_local]
    __shared__ float partial[8][33];
    int n0 = blockIdx.x * 32;
    int k0 = blockIdx.y * 32;
    int tx = threadIdx.x, ty = threadIdx.y;   // 32 x 8
    float sq = 0.f;
#pragma unroll
    for (int i = 0; i < 32; i += 8) {
        float v = p[(size_t)(k0 + ty + i) * OUTDIM + n0 + tx];
        tile[ty + i][tx] = v;
    }
    __syncthreads();
#pragma unroll
    for (int i = 0; i < 4; i++) {
        float v = tile[ty + i * 8][tx];
        sq += v * v;
    }
    partial[ty][tx] = sq;
#pragma unroll
    for (int i = 0; i < 32; i += 8)
        g_pt_fp8[(size_t)(n0 + ty + i) * INDIM + k0 + tx] =
            to_e4m3(32.0f * tile[tx][ty + i]);
    __syncthreads();
    if (ty == 0) {
        float s = 0.f;
#pragma unroll
        for (int j = 0; j < 8; j++) s += partial[j][tx];
        atomicAdd(&g_p_sq[n0 + tx], s);
    }
}

// ---------------- stage loader (256 threads) ----------------
__device__ __forceinline__ void load_stage(uint32_t smem_base, int buf, int m0, int n0,
                                           int k0, int tid) {
    uint32_t a_s = smem_base + SMEM_TILES_OFF + (uint32_t)buf * STAGE_BYTES;
    uint32_t b_s = a_s + BM * 128u;
    const uint8_t* abase = g_x_fp8 + (size_t)m0 * INDIM + k0;
#pragma unroll
    for (int i = 0; i < (BM * 8) / GEMM_THREADS; i++) {   // 4 chunks/thread
        int idx = tid + i * GEMM_THREADS;
        int r = idx >> 3, c = idx & 7;
        cp_async16(a_s + sw128((uint32_t)(r * 128 + c * 16)),
                   abase + (size_t)r * INDIM + c * 16);
    }
    const uint8_t* bbase = g_pt_fp8 + (size_t)n0 * INDIM + k0;
#pragma unroll
    for (int i = 0; i < (BN * 8) / GEMM_THREADS; i++) {   // 4 chunks/thread
        int idx = tid + i * GEMM_THREADS;
        int r = idx >> 3, c = idx & 7;
        cp_async16(b_s + sw128((uint32_t)(r * 128 + c * 16)),
                   bbase + (size_t)r * INDIM + c * 16);
    }
}

// ---------------- GEMM: fp8 mma.sync + fp16 acc, 8 warps x (32x64), 2 CTAs/SM ----------
__global__ void __launch_bounds__(GEMM_THREADS, 2)
gemm_kernel(float* __restrict__ out) {
    extern __shared__ char smem[];
    uint32_t smem_base = smem_to_u32(smem);
    const int tid = threadIdx.x;
    const int wid = tid >> 5;
    const int lid = tid & 31;
    const int wm = wid & 3;         // 4 warps along M (32 rows each)
    const int wn = wid >> 2;        // 2 warps along N (64 cols each)
    const int n0 = blockIdx.x * BN;
    const int m0 = blockIdx.y * BM;

    // stage p_sq tile
    for (int i = tid; i < BN; i += GEMM_THREADS)
        *reinterpret_cast<float*>(smem + SMEM_PSQ_OFF + i * 4) = g_p_sq[n0 + i];

    uint32_t acc[2][8][2];          // fp16x2 accumulators
#pragma unroll
    for (int mi = 0; mi < 2; mi++)
#pragma unroll
        for (int nt = 0; nt < 8; nt++) {
            acc[mi][nt][0] = 0u; acc[mi][nt][1] = 0u;
        }

    // prologue: stages 0..1
#pragma unroll
    for (int s = 0; s < STAGES - 1; s++) {
        load_stage(smem_base, s, m0, n0, s * BK, tid);
        CP_COMMIT();
    }

    // per-lane ldmatrix row/offset components
    const int a_row = wm * 32 + (lid & 15);                   // + mi*16
    const int a_kb  = (lid >> 4) * 16;
    const int sub   = lid >> 3;
    const int b_row = wn * 64 + (sub >> 1) * 8 + (lid & 7);   // + nj*16
    const int b_kb  = (sub & 1) * 16;

    int buf = 0;
    int pbuf = STAGES - 1;          // buffer to prefetch into
    for (int s = 0; s < NSTAGE_K; s++) {
        CP_WAIT(STAGES - 2);                   // stage s landed (this thread)
        __syncthreads();                       // landed for all; all finished compute(s-1)
        if (s + STAGES - 1 < NSTAGE_K)
            load_stage(smem_base, pbuf, m0, n0, (s + STAGES - 1) * BK, tid);
        CP_COMMIT();                           // empty group when no loads

        uint32_t a_s = smem_base + SMEM_TILES_OFF + (uint32_t)buf * STAGE_BYTES;
        uint32_t b_s = a_s + BM * 128u;

#pragma unroll
        for (int ks = 0; ks < BK / 32; ks++) { // 4 k-chunks of 32 bytes
            const int k0b = ks * 32;
            uint32_t afrag[2][4];
#pragma unroll
            for (int mi = 0; mi < 2; mi++) {
                uint32_t off = (uint32_t)((a_row + mi * 16) * 128 + k0b + a_kb);
                ldmatrix_x4(afrag[mi], a_s + sw128(off));
            }
            uint32_t bfrag[8][2];
#pragma unroll
            for (int nj = 0; nj < 4; nj++) {
                uint32_t off = (uint32_t)((b_row + nj * 16) * 128 + k0b + b_kb);
                uint32_t t[4];
                ldmatrix_x4(t, b_s + sw128(off));
                bfrag[nj * 2][0] = t[0]; bfrag[nj * 2][1] = t[1];
                bfrag[nj * 2 + 1][0] = t[2]; bfrag[nj * 2 + 1][1] = t[3];
            }
#pragma unroll
            for (int mi = 0; mi < 2; mi++)
#pragma unroll
                for (int nt = 0; nt < 8; nt++)
                    mma_fp8_h(acc[mi][nt], afrag[mi], bfrag[nt]);
        }
        buf = (buf + 1 == STAGES) ? 0 : buf + 1;
        pbuf = (pbuf + 1 == STAGES) ? 0 : pbuf + 1;
    }

    // fused epilogue: out = (2/32)*acc - x_sq[m] - p_sq[n]
    const float* psq_s = reinterpret_cast<const float*>(smem + SMEM_PSQ_OFF);
    const int lane4 = lid >> 2;
    const int lane2 = (lid & 3) * 2;
#pragma unroll
    for (int mi = 0; mi < 2; mi++) {
#pragma unroll
        for (int h = 0; h < 2; h++) {
            const int r = m0 + wm * 32 + mi * 16 + lane4 + h * 8;
            const float xs = g_x_sq[r];
            float* orow = out + (size_t)r * OUTDIM + n0 + wn * 64;
#pragma unroll
            for (int nt = 0; nt < 8; nt++) {
                const int cn = nt * 8 + lane2;
                __half2 hv = *reinterpret_cast<const __half2*>(&acc[mi][nt][h]);
                float2 w;
                w.x = fmaf(ACC_SCALE, __half2float(__low2half(hv)),
                           -xs - psq_s[wn * 64 + cn]);
                w.y = fmaf(ACC_SCALE, __half2float(__high2half(hv)),
                           -xs - psq_s[wn * 64 + cn + 1]);
                *reinterpret_cast<float2*>(orow + cn) = w;
            }
        }
    }
}

// ---------------- launch ----------------
extern "C" void kernel_launch(void* const* d_in, const int* in_sizes, int n_in,
                              void* d_out, int out_size) {
    const float* x = (const float*)d_in[0];
    const float* p = (const float*)d_in[1];
    if (n_in >= 2 && in_sizes[0] == OUTDIM * INDIM && in_sizes[1] == BATCH * INDIM) {
        x = (const float*)d_in[1];
        p = (const float*)d_in[0];
    }
    float* out = (float*)d_out;

    convert_x_kernel<<<BATCH, 256>>>(x);             // also zeroes g_p_sq
    transpose_psq_kernel<<<dim3(OUTDIM / 32, INDIM / 32), dim3(32, 8)>>>(p);

    cudaFuncSetAttribute(gemm_kernel, cudaFuncAttributeMaxDynamicSharedMemorySize,
                         SMEM_TOTAL);
    gemm_kernel<<<dim3(OUTDIM / BN, BATCH / BM), GEMM_THREADS, SMEM_TOTAL>>>(out);
}

// round 7
// speedup vs baseline: 2.7164x; 1.0397x over previous
#include <cuda_runtime.h>
#include <cuda_bf16.h>
#include <cuda_fp16.h>
#include <cuda_fp8.h>
#include <cstdint>
#include <cstddef>

// ---------------- problem constants ----------------
#define INDIM  1024
#define OUTDIM 2048
#define BATCH  8192

#define BM 128
#define BN 128
#define BK 128                   // fp8 elems per stage = 128 B row (swizzle atom)
#define NSTAGE_K (INDIM / BK)    // 8
#define STAGES 3
#define GEMM_THREADS 256

// P is scaled by 32 before fp8 quantization; epilogue multiplies acc by 2/32.
#define ACC_SCALE 0.0625f

#define SMEM_PSQ_OFF   0u
#define SMEM_TILES_OFF 1024u
#define STAGE_BYTES    ((BM + BN) * 128u)                       // 32768
#define SMEM_TOTAL     (SMEM_TILES_OFF + STAGES * STAGE_BYTES)  // 99328 (x2 CTAs = 194KB/SM)

// prep grid split
#define CONV_BLOCKS  (BATCH / 8)          // 1024 blocks, 8 rows each (warp-per-row)
#define TR_NBLK      (OUTDIM / 32)        // 64
#define TR_KBLK      (INDIM / 32)         // 32
#define PREP_BLOCKS  (CONV_BLOCKS + TR_NBLK * TR_KBLK)   // 3072

// ---------------- device scratch (alloc-free) ----------------
__device__ __align__(128) uint8_t g_x_fp8[(size_t)BATCH * INDIM];   // 8 MB, e4m3
__device__ __align__(128) uint8_t g_pt_fp8[(size_t)OUTDIM * INDIM]; // 2 MB, [n][k], e4m3 of 32*p
__device__ float g_x_sq[BATCH];
__device__ float g_psq_part[TR_KBLK][OUTDIM];   // 256 KB partial column norms

// ---------------- helpers ----------------
__device__ __forceinline__ uint32_t smem_to_u32(const void* p) {
    uint32_t a;
    asm("{ .reg .u64 t; cvta.to.shared.u64 t, %1; cvt.u32.u64 %0, t; }" : "=r"(a) : "l"(p));
    return a;
}
__device__ __forceinline__ uint32_t sw128(uint32_t off) {
    return off ^ ((off >> 3) & 0x70);
}
__device__ __forceinline__ void cp_async16(uint32_t dst, const void* src) {
    asm volatile("cp.async.cg.shared.global [%0], [%1], 16;" :: "r"(dst), "l"(src) : "memory");
}
#define CP_COMMIT() asm volatile("cp.async.commit_group;" ::: "memory")
#define CP_WAIT(n)  asm volatile("cp.async.wait_group %0;" :: "n"(n) : "memory")

__device__ __forceinline__ void ldmatrix_x4(uint32_t* r, uint32_t addr) {
    asm volatile("ldmatrix.sync.aligned.m8n8.x4.shared.b16 {%0,%1,%2,%3}, [%4];"
                 : "=r"(r[0]), "=r"(r[1]), "=r"(r[2]), "=r"(r[3]) : "r"(addr));
}
// fp8 e4m3 MMA with fp16 accumulator (2 packed f16x2 regs).
__device__ __forceinline__ void mma_fp8_h(uint32_t* c, const uint32_t* a, const uint32_t* b) {
    asm volatile(
        "mma.sync.aligned.m16n8k32.row.col.f16.e4m3.e4m3.f16 "
        "{%0,%1}, {%2,%3,%4,%5}, {%6,%7}, {%0,%1};"
        : "+r"(c[0]), "+r"(c[1])
        : "r"(a[0]), "r"(a[1]), "r"(a[2]), "r"(a[3]), "r"(b[0]), "r"(b[1]));
}

__device__ __forceinline__ uint8_t to_e4m3(float v) {
    return (uint8_t)__nv_cvt_float_to_fp8(v, __NV_SATFINITE, __NV_E4M3);
}

// ---------------- fused prep kernel ----------------
// blocks [0, CONV_BLOCKS): convert x -> fp8 + row norms. 8 warps, warp-per-row.
// blocks [CONV_BLOCKS, PREP_BLOCKS): transpose+quantize P, write psq partials.
__global__ void prep_kernel(const float* __restrict__ x, const float* __restrict__ p) {
    const int tid = threadIdx.x;
    if ((int)blockIdx.x < CONV_BLOCKS) {
        const int warp = tid >> 5, lane = tid & 31;
        const int row = blockIdx.x * 8 + warp;
        const float4* xr = reinterpret_cast<const float4*>(x + (size_t)row * INDIM);
        uchar4* dst = reinterpret_cast<uchar4*>(g_x_fp8 + (size_t)row * INDIM);
        float acc = 0.f;
        float4 v[8];
#pragma unroll
        for (int j = 0; j < 8; j++) v[j] = xr[lane + 32 * j];
#pragma unroll
        for (int j = 0; j < 8; j++) {
            acc += v[j].x * v[j].x + v[j].y * v[j].y + v[j].z * v[j].z + v[j].w * v[j].w;
            uchar4 q;
            q.x = to_e4m3(v[j].x); q.y = to_e4m3(v[j].y);
            q.z = to_e4m3(v[j].z); q.w = to_e4m3(v[j].w);
            dst[lane + 32 * j] = q;
        }
#pragma unroll
        for (int o = 16; o > 0; o >>= 1) acc += __shfl_xor_sync(0xFFFFFFFFu, acc, o);
        if (lane == 0) g_x_sq[row] = acc;
    } else {
        __shared__ float tile[32][33];     // tile[k_local][n_local]
        __shared__ float partial[8][33];
        const int b2 = blockIdx.x - CONV_BLOCKS;
        const int n0 = (b2 % TR_NBLK) * 32;
        const int k_blk = b2 / TR_NBLK;
        const int k0 = k_blk * 32;
        const int tx = tid & 31, ty = tid >> 5;   // 32 x 8
#pragma unroll
        for (int i = 0; i < 32; i += 8)
            tile[ty + i][tx] = p[(size_t)(k0 + ty + i) * OUTDIM + n0 + tx];
        __syncthreads();
        float sq = 0.f;
#pragma unroll
        for (int i = 0; i < 4; i++) {
            float v = tile[ty + i * 8][tx];
            sq += v * v;
        }
        partial[ty][tx] = sq;
#pragma unroll
        for (int i = 0; i < 32; i += 8)
            g_pt_fp8[(size_t)(n0 + ty + i) * INDIM + k0 + tx] =
                to_e4m3(32.0f * tile[tx][ty + i]);
        __syncthreads();
        if (ty == 0) {
            float s = 0.f;
#pragma unroll
            for (int j = 0; j < 8; j++) s += partial[j][tx];
            g_psq_part[k_blk][n0 + tx] = s;    // deterministic overwrite, no atomics
        }
    }
}

// ---------------- stage loader (256 threads) ----------------
__device__ __forceinline__ void load_stage(uint32_t smem_base, int buf, int m0, int n0,
                                           int k0, int tid) {
    uint32_t a_s = smem_base + SMEM_TILES_OFF + (uint32_t)buf * STAGE_BYTES;
    uint32_t b_s = a_s + BM * 128u;
    const uint8_t* abase = g_x_fp8 + (size_t)m0 * INDIM + k0;
#pragma unroll
    for (int i = 0; i < (BM * 8) / GEMM_THREADS; i++) {   // 4 chunks/thread
        int idx = tid + i * GEMM_THREADS;
        int r = idx >> 3, c = idx & 7;
        cp_async16(a_s + sw128((uint32_t)(r * 128 + c * 16)),
                   abase + (size_t)r * INDIM + c * 16);
    }
    const uint8_t* bbase = g_pt_fp8 + (size_t)n0 * INDIM + k0;
#pragma unroll
    for (int i = 0; i < (BN * 8) / GEMM_THREADS; i++) {   // 4 chunks/thread
        int idx = tid + i * GEMM_THREADS;
        int r = idx >> 3, c = idx & 7;
        cp_async16(b_s + sw128((uint32_t)(r * 128 + c * 16)),
                   bbase + (size_t)r * INDIM + c * 16);
    }
}

// ---------------- GEMM: fp8 mma.sync + fp16 acc, 8 warps x (32x64), 2 CTAs/SM ----------
__global__ void __launch_bounds__(GEMM_THREADS, 2)
gemm_kernel(float* __restrict__ out) {
    extern __shared__ char smem[];
    uint32_t smem_base = smem_to_u32(smem);
    const int tid = threadIdx.x;
    const int wid = tid >> 5;
    const int lid = tid & 31;
    const int wm = wid & 3;         // 4 warps along M (32 rows each)
    const int wn = wid >> 2;        // 2 warps along N (64 cols each)
    const int n0 = blockIdx.x * BN;
    const int m0 = blockIdx.y * BM;

    // prologue loads first so the psq reduction below overlaps the cp.async latency
#pragma unroll
    for (int s = 0; s < STAGES - 1; s++) {
        load_stage(smem_base, s, m0, n0, s * BK, tid);
        CP_COMMIT();
    }

    // reduce psq partials into smem tile: psq[n] = sum_k g_psq_part[k][n]
    for (int i = tid; i < BN; i += GEMM_THREADS) {
        float s0 = 0.f, s1 = 0.f, s2 = 0.f, s3 = 0.f;
#pragma unroll
        for (int j = 0; j < TR_KBLK; j += 4) {
            s0 += g_psq_part[j + 0][n0 + i];
            s1 += g_psq_part[j + 1][n0 + i];
            s2 += g_psq_part[j + 2][n0 + i];
            s3 += g_psq_part[j + 3][n0 + i];
        }
        *reinterpret_cast<float*>(smem + SMEM_PSQ_OFF + i * 4) = (s0 + s1) + (s2 + s3);
    }

    uint32_t acc[2][8][2];          // fp16x2 accumulators
#pragma unroll
    for (int mi = 0; mi < 2; mi++)
#pragma unroll
        for (int nt = 0; nt < 8; nt++) {
            acc[mi][nt][0] = 0u; acc[mi][nt][1] = 0u;
        }

    // per-lane ldmatrix row/offset components
    const int a_row = wm * 32 + (lid & 15);                   // + mi*16
    const int a_kb  = (lid >> 4) * 16;
    const int sub   = lid >> 3;
    const int b_row = wn * 64 + (sub >> 1) * 8 + (lid & 7);   // + nj*16
    const int b_kb  = (sub & 1) * 16;

    int buf = 0;
    int pbuf = STAGES - 1;          // buffer to prefetch into
    for (int s = 0; s < NSTAGE_K; s++) {
        CP_WAIT(STAGES - 2);                   // stage s landed (this thread)
        __syncthreads();                       // landed for all; all finished compute(s-1)
        if (s + STAGES - 1 < NSTAGE_K)
            load_stage(smem_base, pbuf, m0, n0, (s + STAGES - 1) * BK, tid);
        CP_COMMIT();                           // empty group when no loads

        uint32_t a_s = smem_base + SMEM_TILES_OFF + (uint32_t)buf * STAGE_BYTES;
        uint32_t b_s = a_s + BM * 128u;

#pragma unroll
        for (int ks = 0; ks < BK / 32; ks++) { // 4 k-chunks of 32 bytes
            const int k0b = ks * 32;
            uint32_t afrag[2][4];
#pragma unroll
            for (int mi = 0; mi < 2; mi++) {
                uint32_t off = (uint32_t)((a_row + mi * 16) * 128 + k0b + a_kb);
                ldmatrix_x4(afrag[mi], a_s + sw128(off));
            }
            uint32_t bfrag[8][2];
#pragma unroll
            for (int nj = 0; nj < 4; nj++) {
                uint32_t off = (uint32_t)((b_row + nj * 16) * 128 + k0b + b_kb);
                uint32_t t[4];
                ldmatrix_x4(t, b_s + sw128(off));
                bfrag[nj * 2][0] = t[0]; bfrag[nj * 2][1] = t[1];
                bfrag[nj * 2 + 1][0] = t[2]; bfrag[nj * 2 + 1][1] = t[3];
            }
#pragma unroll
            for (int mi = 0; mi < 2; mi++)
#pragma unroll
                for (int nt = 0; nt < 8; nt++)
                    mma_fp8_h(acc[mi][nt], afrag[mi], bfrag[nt]);
        }
        buf = (buf + 1 == STAGES) ? 0 : buf + 1;
        pbuf = (pbuf + 1 == STAGES) ? 0 : pbuf + 1;
    }

    // fused epilogue: out = (2/32)*acc - x_sq[m] - p_sq[n]
    const float* psq_s = reinterpret_cast<const float*>(smem + SMEM_PSQ_OFF);
    const int lane4 = lid >> 2;
    const int lane2 = (lid & 3) * 2;
#pragma unroll
    for (int mi = 0; mi < 2; mi++) {
#pragma unroll
        for (int h = 0; h < 2; h++) {
            const int r = m0 + wm * 32 + mi * 16 + lane4 + h * 8;
            const float xs = g_x_sq[r];
            float* orow = out + (size_t)r * OUTDIM + n0 + wn * 64;
#pragma unroll
            for (int nt = 0; nt < 8; nt++) {
                const int cn = nt * 8 + lane2;
                __half2 hv = *reinterpret_cast<const __half2*>(&acc[mi][nt][h]);
                float2 w;
                w.x = fmaf(ACC_SCALE, __half2float(__low2half(hv)),
                           -xs - psq_s[wn * 64 + cn]);
                w.y = fmaf(ACC_SCALE, __half2float(__high2half(hv)),
                           -xs - psq_s[wn * 64 + cn + 1]);
                *reinterpret_cast<float2*>(orow + cn) = w;
            }
        }
    }
}

// ---------------- launch ----------------
extern "C" void kernel_launch(void* const* d_in, const int* in_sizes, int n_in,
                              void* d_out, int out_size) {
    const float* x = (const float*)d_in[0];
    const float* p = (const float*)d_in[1];
    if (n_in >= 2 && in_sizes[0] == OUTDIM * INDIM && in_sizes[1] == BATCH * INDIM) {
        x = (const float*)d_in[1];
        p = (const float*)d_in[0];
    }
    float* out = (float*)d_out;

    prep_kernel<<<PREP_BLOCKS, 256>>>(x, p);

    cudaFuncSetAttribute(gemm_kernel, cudaFuncAttributeMaxDynamicSharedMemorySize,
                         SMEM_TOTAL);
    gemm_kernel<<<dim3(OUTDIM / BN, BATCH / BM), GEMM_THREADS, SMEM_TOTAL>>>(out);
}